// round 3
// baseline (speedup 1.0000x reference)
#include <cuda_runtime.h>
#include <cuda_fp16.h>
#include <cstdint>

// ----------------------------------------------------------------------------
// Problem constants
// ----------------------------------------------------------------------------
#define GRID_G   8
#define IN_DIM   1024
#define OUT_DIM  1024
#define BATCH    4096
#define NFEAT    17                    // [silu, cos(1..8 x), sin(1..8 x)]
#define KDIM     (IN_DIM * NFEAT)      // 17408
#define TK       64
#define NK       (KDIM / TK)           // 272
#define TM       128
#define TN       256
#define NSTAGES  4
#define A_STAGE  (TM * 128)            // 16384 B (128 rows x 64 halfs)
#define B_STAGE  (TN * 128)            // 32768 B
#define STAGE    (A_STAGE + B_STAGE)   // 49152 B
#define SMEM_SIZE (NSTAGES * STAGE)    // 196608 B

// ----------------------------------------------------------------------------
// Scratch (device globals: sanctioned alloc-free workaround)
// ----------------------------------------------------------------------------
__device__ __half g_F[(size_t)BATCH * KDIM];    // features (B, K')
__device__ __half g_W[(size_t)OUT_DIM * KDIM];  // weights  (O, K')

// ----------------------------------------------------------------------------
// Helpers
// ----------------------------------------------------------------------------
__device__ __forceinline__ uint32_t smem_u32(const void* p) {
    uint32_t a;
    asm("{ .reg .u64 t; cvta.to.shared.u64 t, %1; cvt.u32.u64 %0, t; }"
        : "=r"(a) : "l"(p));
    return a;
}

// 128B-row swizzle: XOR row bits [9:7] into 16B-chunk bits [6:4]
__device__ __forceinline__ uint32_t swz(uint32_t o) {
    return o ^ ((o >> 3) & 0x70);
}

#define CP_ASYNC16(saddr, gaddr) \
    asm volatile("cp.async.cg.shared.global [%0], [%1], 16;" \
        :: "r"(saddr), "l"(gaddr) : "memory")
#define CP_COMMIT() asm volatile("cp.async.commit_group;" ::: "memory")
#define CP_WAIT2()  asm volatile("cp.async.wait_group 2;" ::: "memory")

#define LDSM_X4(r0, r1, r2, r3, addr) \
    asm volatile("ldmatrix.sync.aligned.m8n8.x4.shared.b16 {%0,%1,%2,%3}, [%4];" \
        : "=r"(r0), "=r"(r1), "=r"(r2), "=r"(r3) : "r"(addr))

#define MMA16816(c0, c1, c2, c3, a0, a1, a2, a3, b0, b1) \
    asm volatile( \
        "mma.sync.aligned.m16n8k16.row.col.f32.f16.f16.f32 " \
        "{%0,%1,%2,%3}, {%4,%5,%6,%7}, {%8,%9}, {%0,%1,%2,%3};" \
        : "+f"(c0), "+f"(c1), "+f"(c2), "+f"(c3) \
        : "r"(a0), "r"(a1), "r"(a2), "r"(a3), "r"(b0), "r"(b1))

// ----------------------------------------------------------------------------
// Kernel 1: feature build.  F[b][f*1024 + i], fp16.
//   f0 = silu(x);  f1..8 = cos(g x);  f9..16 = sin(g x)
// ----------------------------------------------------------------------------
__global__ void __launch_bounds__(256) build_features(
    const float* __restrict__ x, __half* __restrict__ F) {
    int t = blockIdx.x * 256 + threadIdx.x;           // 2 input elems per thread
    int b = t >> 9;
    int i2 = (t & 511) << 1;
    float2 xv = *reinterpret_cast<const float2*>(x + (size_t)b * IN_DIM + i2);
    float ft[2][NFEAT];
#pragma unroll
    for (int u = 0; u < 2; u++) {
        float xx = (u == 0) ? xv.x : xv.y;
        float sg = 1.0f / (1.0f + __expf(-xx));
        ft[u][0] = xx * sg;
        float s1, c1;
        sincosf(xx, &s1, &c1);
        float ck = c1, sk = s1;
        ft[u][1] = ck; ft[u][9] = sk;
#pragma unroll
        for (int g = 1; g < GRID_G; g++) {
            float cn = fmaf(ck, c1, -sk * s1);
            float sn = fmaf(sk, c1,  ck * s1);
            ck = cn; sk = sn;
            ft[u][1 + g] = ck; ft[u][9 + g] = sk;
        }
    }
    __half* Fr = F + (size_t)b * KDIM + i2;
#pragma unroll
    for (int f = 0; f < NFEAT; f++) {
        __half2 v;
        v.x = __float2half_rn(ft[0][f]);
        v.y = __float2half_rn(ft[1][f]);
        *reinterpret_cast<__half2*>(Fr + (size_t)f * IN_DIM) = v;
    }
}

// ----------------------------------------------------------------------------
// Kernel 2: weight build. W[o][f*1024 + i], fp16.
//   f0 = sb;  f1..8 = ss*coeff[0,o,i,g];  f9..16 = ss*coeff[1,o,i,g]
// ----------------------------------------------------------------------------
__global__ void __launch_bounds__(256) build_weights(
    const float* __restrict__ sb, const float* __restrict__ ss,
    const float* __restrict__ cf, __half* __restrict__ W) {
    int t = blockIdx.x * 256 + threadIdx.x;
    int o = t >> 9;
    int i2 = (t & 511) << 1;
    float w[2][NFEAT];
#pragma unroll
    for (int u = 0; u < 2; u++) {
        size_t oi = (size_t)o * IN_DIM + (i2 + u);
        w[u][0] = sb[oi];
        float s = ss[oi];
        const float4* c0 = reinterpret_cast<const float4*>(cf + oi * GRID_G);
        const float4* c1 = reinterpret_cast<const float4*>(
            cf + ((size_t)OUT_DIM * IN_DIM + oi) * GRID_G);
        float4 a0 = c0[0], a1 = c0[1], b0 = c1[0], b1 = c1[1];
        w[u][1]  = s * a0.x; w[u][2]  = s * a0.y; w[u][3]  = s * a0.z; w[u][4]  = s * a0.w;
        w[u][5]  = s * a1.x; w[u][6]  = s * a1.y; w[u][7]  = s * a1.z; w[u][8]  = s * a1.w;
        w[u][9]  = s * b0.x; w[u][10] = s * b0.y; w[u][11] = s * b0.z; w[u][12] = s * b0.w;
        w[u][13] = s * b1.x; w[u][14] = s * b1.y; w[u][15] = s * b1.z; w[u][16] = s * b1.w;
    }
    __half* Wr = W + (size_t)o * KDIM + i2;
#pragma unroll
    for (int f = 0; f < NFEAT; f++) {
        __half2 v;
        v.x = __float2half_rn(w[0][f]);
        v.y = __float2half_rn(w[1][f]);
        *reinterpret_cast<__half2*>(Wr + (size_t)f * IN_DIM) = v;
    }
}

// ----------------------------------------------------------------------------
// Kernel 3: GEMM  out(4096x1024) = F(4096xK') * W(1024xK')^T
// cp.async 4-stage pipeline + ldmatrix + mma.sync.m16n8k16 (fp16 -> fp32)
// 512 threads = 16 warps in 4(M) x 4(N); warp tile 32x64.
// ----------------------------------------------------------------------------
__device__ __forceinline__ void issue_stage(
    uint32_t smem_base, int slot, int kb,
    const __half* __restrict__ F, const __half* __restrict__ W,
    int tid, int m0, int n0) {
    uint32_t abase = smem_base + slot * STAGE;
    uint32_t bbase = abase + A_STAGE;
    int k0 = kb * TK;
    // A: 1024 16B-chunks (128 rows x 8)
#pragma unroll
    for (int j = 0; j < 2; j++) {
        int c = tid + 512 * j;
        int row = c >> 3, kc = c & 7;
        const __half* g = F + (size_t)(m0 + row) * KDIM + k0 + kc * 8;
        CP_ASYNC16(abase + swz(row * 128 + kc * 16), g);
    }
    // B: 2048 16B-chunks (256 rows x 8)
#pragma unroll
    for (int j = 0; j < 4; j++) {
        int c = tid + 512 * j;
        int row = c >> 3, kc = c & 7;
        const __half* g = W + (size_t)(n0 + row) * KDIM + k0 + kc * 8;
        CP_ASYNC16(bbase + swz(row * 128 + kc * 16), g);
    }
}

__global__ void __launch_bounds__(512, 1) kan_gemm(
    const __half* __restrict__ F, const __half* __restrict__ W,
    float* __restrict__ out) {
    extern __shared__ __align__(1024) char smem[];
    uint32_t sbm = smem_u32(smem);
    int tid = threadIdx.x, wid = tid >> 5, lane = tid & 31;
    int m0 = blockIdx.x * TM, n0 = blockIdx.y * TN;
    int wm = wid & 3, wn = wid >> 2;          // warp tile: rows wm*32, cols wn*64

    float acc[2][8][4];
#pragma unroll
    for (int mi = 0; mi < 2; mi++)
#pragma unroll
        for (int ni = 0; ni < 8; ni++)
#pragma unroll
            for (int r = 0; r < 4; r++) acc[mi][ni][r] = 0.0f;

    // ldmatrix lane-address components (constant over k loop)
    int lrow8 = lane & 7;
    int ltile = lane >> 3;                    // 0..3
    // A tiles: T0 r0-7/k0-7, T1 r8-15/k0-7, T2 r0-7/k8-15, T3 r8-15/k8-15
    int a_row_off = (ltile & 1) * 8 + lrow8;
    int a_k_off   = (ltile >> 1) * 8;
    // B tiles: T0 n0-7/k0-7, T1 n0-7/k8-15, T2 n8-15/k0-7, T3 n8-15/k8-15
    int b_row_off = (ltile >> 1) * 8 + lrow8;
    int b_k_off   = (ltile & 1) * 8;

    // prologue: fill 3 stages
    issue_stage(sbm, 0, 0, F, W, tid, m0, n0); CP_COMMIT();
    issue_stage(sbm, 1, 1, F, W, tid, m0, n0); CP_COMMIT();
    issue_stage(sbm, 2, 2, F, W, tid, m0, n0); CP_COMMIT();

    for (int kb = 0; kb < NK; kb++) {
        int s = kb & 3;
        CP_WAIT2();
        __syncthreads();
        if (kb + 3 < NK)
            issue_stage(sbm, (kb + 3) & 3, kb + 3, F, W, tid, m0, n0);
        CP_COMMIT();

        uint32_t abase = sbm + s * STAGE;
        uint32_t bbase = abase + A_STAGE;
#pragma unroll
        for (int ks = 0; ks < 4; ks++) {
            uint32_t a[2][4];
#pragma unroll
            for (int mi = 0; mi < 2; mi++) {
                int row = wm * 32 + mi * 16 + a_row_off;
                int ko = ks * 16 + a_k_off;
                LDSM_X4(a[mi][0], a[mi][1], a[mi][2], a[mi][3],
                        abase + swz(row * 128 + ko * 2));
            }
            uint32_t b[4][4];
#pragma unroll
            for (int ng = 0; ng < 4; ng++) {
                int row = wn * 64 + ng * 16 + b_row_off;
                int ko = ks * 16 + b_k_off;
                LDSM_X4(b[ng][0], b[ng][1], b[ng][2], b[ng][3],
                        bbase + swz(row * 128 + ko * 2));
            }
#pragma unroll
            for (int mi = 0; mi < 2; mi++)
#pragma unroll
                for (int ni = 0; ni < 8; ni++) {
                    int ng = ni >> 1, pr = (ni & 1) * 2;
                    MMA16816(acc[mi][ni][0], acc[mi][ni][1],
                             acc[mi][ni][2], acc[mi][ni][3],
                             a[mi][0], a[mi][1], a[mi][2], a[mi][3],
                             b[ng][pr], b[ng][pr + 1]);
                }
        }
        __syncthreads();
    }

    // epilogue: direct float2 stores
#pragma unroll
    for (int mi = 0; mi < 2; mi++) {
        int r = m0 + wm * 32 + mi * 16 + (lane >> 2);
#pragma unroll
        for (int ni = 0; ni < 8; ni++) {
            int c = n0 + wn * 64 + ni * 8 + (lane & 3) * 2;
            float2 v0 = make_float2(acc[mi][ni][0], acc[mi][ni][1]);
            float2 v1 = make_float2(acc[mi][ni][2], acc[mi][ni][3]);
            *reinterpret_cast<float2*>(out + (size_t)r * OUT_DIM + c) = v0;
            *reinterpret_cast<float2*>(out + (size_t)(r + 8) * OUT_DIM + c) = v1;
        }
    }
}

// ----------------------------------------------------------------------------
// Host launcher
// ----------------------------------------------------------------------------
extern "C" void kernel_launch(void* const* d_in, const int* in_sizes, int n_in,
                              void* d_out, int out_size) {
    // Identify inputs by element count (dict order: x, scale_base, scale_spline, coeff)
    const float *x = nullptr, *sbp = nullptr, *ssp = nullptr, *cfp = nullptr;
    for (int i = 0; i < n_in; i++) {
        if (in_sizes[i] == BATCH * IN_DIM)                     x   = (const float*)d_in[i];
        else if (in_sizes[i] == 2 * OUT_DIM * IN_DIM * GRID_G) cfp = (const float*)d_in[i];
        else if (in_sizes[i] == OUT_DIM * IN_DIM) {
            if (!sbp) sbp = (const float*)d_in[i];
            else      ssp = (const float*)d_in[i];
        }
    }
    float* out = (float*)d_out;

    void *pF = nullptr, *pW = nullptr;
    cudaGetSymbolAddress(&pF, g_F);
    cudaGetSymbolAddress(&pW, g_W);

    build_features<<<BATCH * (IN_DIM / 2) / 256, 256>>>(x, (__half*)pF);
    build_weights<<<OUT_DIM * (IN_DIM / 2) / 256, 256>>>(sbp, ssp, cfp, (__half*)pW);

    cudaFuncSetAttribute(kan_gemm,
                         cudaFuncAttributeMaxDynamicSharedMemorySize, SMEM_SIZE);
    kan_gemm<<<dim3(BATCH / TM, OUT_DIM / TN), 512, SMEM_SIZE>>>(
        (const __half*)pF, (const __half*)pW, out);
}